// round 5
// baseline (speedup 1.0000x reference)
#include <cuda_runtime.h>

#define BB 2
#define CC 128
#define TT 5
#define HH 48
#define WW 48
#define HWP 2304      // H*W
#define NH 64         // heads (half channels)
#define TC 4          // context frames
#define PAD 3
#define NK 196        // Tc * 7 * 7
#define NQ2 36        // HWP / 64 (out-proj pixel chunks)

// Scratch (allocation-free rule: __device__ globals)
__device__ float g_q   [BB * HWP * NH];            // [b][pix][h]
__device__ float g_phi [BB * TC * HWP * NH];       // [b][t][pix][h]   (for QK)
__device__ float g_gvT [BB * NH * TC * HWP];       // [b][h][t][pix]   (for scrambled AV)
__device__ float g_y   [BB * HWP * NH];            // [b][pix][h]      (attention output Y)

#define TP 32  // pixels per projection tile

// ---------------------------------------------------------------------------
// Projection of context frames: phi = w_phi @ x  -> g_phi [b][t][pix][h]
//                               g   = w_g   @ x  -> g_gvT [b][h][t][pix]
// grid = B*TC*(HWP/TP), block = 128 (thread = output row: 0-63 phi, 64-127 g)
// ---------------------------------------------------------------------------
__global__ void proj_ctx_kernel(const float* __restrict__ x,
                                const float* __restrict__ w_phi,
                                const float* __restrict__ w_g) {
    const int nb  = HWP / TP;                  // 72
    int blk  = blockIdx.x;
    int pb   = blk % nb;
    int t    = (blk / nb) % TC;
    int b    = blk / (nb * TC);
    int pix0 = pb * TP;

    __shared__ float xs[CC][TP];               // 16 KB

    const float* xb = x + ((long)(b * CC) * TT + (t + 1)) * HWP + pix0;
    for (int i = threadIdx.x; i < CC * TP; i += blockDim.x) {
        int c = i / TP, pp = i % TP;
        xs[c][pp] = xb[(long)c * TT * HWP + pp];
    }
    __syncthreads();

    int r = threadIdx.x;                       // output row 0..127
    const float* wr = (r < NH) ? (w_phi + r * CC) : (w_g + (r - NH) * CC);

    float acc[TP];
#pragma unroll
    for (int pp = 0; pp < TP; pp++) acc[pp] = 0.f;

    for (int c = 0; c < CC; c++) {
        float w = wr[c];
#pragma unroll
        for (int pp = 0; pp < TP; pp++) acc[pp] += w * xs[c][pp];
    }

    if (r < NH) {
        // phi: [b][t][pix][h]
        long base = ((long)(b * TC + t) * HWP + pix0);
#pragma unroll
        for (int pp = 0; pp < TP; pp++) g_phi[(base + pp) * NH + r] = acc[pp];
    } else {
        // g: [b][h][t][pix] — 32 consecutive floats per thread, float4 stores
        int rr = r - NH;
        float* ob = g_gvT + ((long)(b * NH + rr) * TC + t) * HWP + pix0;
#pragma unroll
        for (int pp = 0; pp < TP; pp += 4) {
            float4 v = make_float4(acc[pp], acc[pp + 1], acc[pp + 2], acc[pp + 3]);
            *(float4*)(ob + pp) = v;
        }
    }
}

// ---------------------------------------------------------------------------
// Projection of query frame (t=0): q = w_theta @ x -> g_q [b][pix][h]
// grid = B*(HWP/TP), block = 64
// ---------------------------------------------------------------------------
__global__ void proj_q_kernel(const float* __restrict__ x,
                              const float* __restrict__ w_theta) {
    const int nb  = HWP / TP;
    int blk  = blockIdx.x;
    int pb   = blk % nb;
    int b    = blk / nb;
    int pix0 = pb * TP;

    __shared__ float xs[CC][TP];

    const float* xb = x + ((long)(b * CC) * TT + 0) * HWP + pix0;
    for (int i = threadIdx.x; i < CC * TP; i += blockDim.x) {
        int c = i / TP, pp = i % TP;
        xs[c][pp] = xb[(long)c * TT * HWP + pp];
    }
    __syncthreads();

    int r = threadIdx.x;                       // 0..63
    const float* wr = w_theta + r * CC;

    float acc[TP];
#pragma unroll
    for (int pp = 0; pp < TP; pp++) acc[pp] = 0.f;

    for (int c = 0; c < CC; c++) {
        float w = wr[c];
#pragma unroll
        for (int pp = 0; pp < TP; pp++) acc[pp] += w * xs[c][pp];
    }

    long base = ((long)b * HWP + pix0);
#pragma unroll
    for (int pp = 0; pp < TP; pp++) g_q[(base + pp) * NH + r] = acc[pp];
}

// ---------------------------------------------------------------------------
// Attention per query pixel: QK, softmax, scrambled AV -> Y[b][pix][h]
// The reference's g_p reshape reinterprets the (h,Tc,pp) block as (K,h):
//   G[k,h'] = g(head=(64k+h')/196, key=(64k+h')%196)
// block = 128 threads, grid = B*HWP
// ---------------------------------------------------------------------------
__global__ void attn_kernel() {
    int bp  = blockIdx.x;               // 0 .. B*HWP-1
    int b   = bp / HWP;
    int pix = bp % HWP;
    int y0  = pix / WW;
    int x0  = pix % WW;
    int tid  = threadIdx.x;
    int warp = tid >> 5;
    int lane = tid & 31;

    __shared__ float qs[NH];
    __shared__ float att[NK];
    __shared__ int   nbr[NK];     // element offset into g_phi ((b,t,pix)*NH)
    __shared__ int   ntp[NK];     // tf*HWP + pix (for g_gvT addressing)
    __shared__ float ypart[2][NH];
    __shared__ float red[8];

    if (tid < NH) qs[tid] = g_q[((long)b * HWP + pix) * NH + tid];

    // neighbor bases (replicate-pad clamp)
    for (int k = tid; k < NK; k += 128) {
        int tf  = k / 49;
        int off = k % 49;
        int dy  = off / 7 - PAD;
        int dx  = off % 7 - PAD;
        int ny  = min(max(y0 + dy, 0), HH - 1);
        int nx  = min(max(x0 + dx, 0), WW - 1);
        int pk  = ny * WW + nx;
        nbr[k] = ((b * TC + tf) * HWP + pk) * NH;
        ntp[k] = tf * HWP + pk;
    }
    __syncthreads();

    // ---- QK: one warp per key, coalesced float2 loads, shfl reduce ----
    for (int k = warp; k < NK; k += 4) {
        const float2* pr = (const float2*)(g_phi + nbr[k]);
        float2 a = pr[lane];
        float d = qs[2 * lane] * a.x + qs[2 * lane + 1] * a.y;
#pragma unroll
        for (int s = 16; s > 0; s >>= 1) d += __shfl_xor_sync(0xffffffffu, d, s);
        if (lane == 0) att[k] = d * 8.0f;     // * sqrt(h)
    }
    __syncthreads();

    // ---- softmax over 196 ----
    float m = -1e30f;
    for (int k = tid; k < NK; k += 128) m = fmaxf(m, att[k]);
#pragma unroll
    for (int s = 16; s > 0; s >>= 1) m = fmaxf(m, __shfl_xor_sync(0xffffffffu, m, s));
    if (lane == 0) red[warp] = m;
    __syncthreads();
    if (tid == 0) red[4] = fmaxf(fmaxf(red[0], red[1]), fmaxf(red[2], red[3]));
    __syncthreads();
    m = red[4];

    float ssum = 0.f;
    for (int k = tid; k < NK; k += 128) {
        float e = __expf(att[k] - m);
        att[k] = e;
        ssum += e;
    }
#pragma unroll
    for (int s = 16; s > 0; s >>= 1) ssum += __shfl_xor_sync(0xffffffffu, ssum, s);
    if (lane == 0) red[warp] = ssum;
    __syncthreads();
    if (tid == 0) red[5] = red[0] + red[1] + red[2] + red[3];
    __syncthreads();
    float inv = 1.f / red[5];
    for (int k = tid; k < NK; k += 128) att[k] *= inv;
    __syncthreads();

    // ---- AV with the reference's scrambled (K,h) reinterpretation ----
    {
        int half = tid >> 6;                  // 0 or 1
        int h    = tid & (NH - 1);
        int kbeg = half ? 98 : 0;
        int kend = half ? NK : 98;

        const float* gbase = g_gvT + (long)b * NH * TC * HWP;

        int f0 = kbeg * NH + h;               // flat index into (h,t,j) block
        int hh = f0 / NK;                     // source head
        int kk = f0 - hh * NK;                // source key (t*49 + j)

        float acc = 0.f;
        for (int k = kbeg; k < kend; k++) {
            acc += att[k] * gbase[hh * (TC * HWP) + ntp[kk]];
            kk += NH;
            if (kk >= NK) { kk -= NK; hh++; }
        }
        ypart[half][h] = acc;
    }
    __syncthreads();
    if (tid < NH)
        g_y[((long)b * HWP + pix) * NH + tid] = ypart[0][tid] + ypart[1][tid];
}

// ---------------------------------------------------------------------------
// Out projection + residual, honoring the reference's y.reshape scramble:
//   out[b,c,p2] = x[b,c,0,p2] + sum_h2 w_out[c,h2] * Y[b, h2*36 + p2/64, p2%64]
// block handles one (b, q2=p2/64, h-half). grid = B*NQ2*2, block = 128 (c=tid).
// ---------------------------------------------------------------------------
#define HHALF 32
__global__ void outproj_kernel(const float* __restrict__ x,
                               const float* __restrict__ w_out,
                               float* __restrict__ out) {
    int blk  = blockIdx.x;
    int half = blk & 1;
    int q2   = (blk >> 1) % NQ2;
    int b    = blk / (2 * NQ2);
    int h0   = half * HHALF;
    int tid  = threadIdx.x;

    __shared__ float ys[NH][HHALF];   // ys[h2][hloc] = Y[b, h2*36+q2, h0+hloc]

    // load 64 rows of 32 consecutive floats (coalesced 128B rows)
    for (int i = tid; i < NH * HHALF; i += 128) {
        int h2   = i / HHALF;
        int hloc = i % HHALF;
        ys[h2][hloc] = g_y[((long)b * HWP + h2 * NQ2 + q2) * NH + h0 + hloc];
    }
    __syncthreads();

    int c = tid;                                   // 0..127
    const float* wr = w_out + c * NH;

    float acc[HHALF];
#pragma unroll
    for (int j = 0; j < HHALF; j++) acc[j] = 0.f;

    for (int h2 = 0; h2 < NH; h2++) {
        float w = wr[h2];
#pragma unroll
        for (int j = 0; j < HHALF; j++) acc[j] += w * ys[h2][j];
    }

    // residual + store: 32 consecutive pixels p2 = q2*64 + h0 + j
    long pixbase = (long)q2 * 64 + h0;
    const float* xr = x + (((long)(b * CC + c)) * TT + 0) * HWP + pixbase;
    float*       orow = out + ((long)(b * CC + c)) * HWP + pixbase;
#pragma unroll
    for (int j = 0; j < HHALF; j += 4) {
        float4 xv = *(const float4*)(xr + j);
        float4 ov = make_float4(xv.x + acc[j],     xv.y + acc[j + 1],
                                xv.z + acc[j + 2], xv.w + acc[j + 3]);
        *(float4*)(orow + j) = ov;
    }
}

extern "C" void kernel_launch(void* const* d_in, const int* in_sizes, int n_in,
                              void* d_out, int out_size) {
    const float* x       = (const float*)d_in[0];
    const float* w_theta = (const float*)d_in[1];
    const float* w_phi   = (const float*)d_in[2];
    const float* w_g     = (const float*)d_in[3];
    const float* w_out   = (const float*)d_in[4];
    float* out = (float*)d_out;

    proj_ctx_kernel<<<BB * TC * (HWP / TP), 128>>>(x, w_phi, w_g);
    proj_q_kernel<<<BB * (HWP / TP), 64>>>(x, w_theta);
    attn_kernel<<<BB * HWP, 128>>>();
    outproj_kernel<<<BB * NQ2 * 2, 128>>>(x, w_out, out);
}

// round 6
// speedup vs baseline: 1.5826x; 1.5826x over previous
#include <cuda_runtime.h>

#define BB 2
#define CC 128
#define TT 5
#define HH 48
#define WW 48
#define HWP 2304      // H*W
#define NH 64         // heads (half channels)
#define TC 4          // context frames
#define PAD 3
#define NK 196        // Tc * 7 * 7
#define NQ2 36        // HWP / 64 (out-proj pixel chunks)
#define FRAME (TC * HWP)

// Scratch (allocation-free rule: __device__ globals)
__device__ float g_q    [BB * HWP * NH];            // [b][pix][h]
__device__ float g_phiT [BB * NH * TC * HWP];       // [b][h][t][pix]  (QK, transposed)
__device__ float g_gvT  [BB * NH * TC * HWP];       // [b][h][t][pix]  (scrambled AV)
__device__ float g_y    [BB * HWP * NH];            // [b][pix][h]

#define TP 32  // pixels per projection tile

// ---------------------------------------------------------------------------
// Context projections: phi -> g_phiT, g -> g_gvT (both [b][h][t][pix])
// grid = B*TC*(HWP/TP), block = 128 (thread = output row: 0-63 phi, 64-127 g)
// ---------------------------------------------------------------------------
__global__ __launch_bounds__(128) void proj_ctx_kernel(
        const float* __restrict__ x,
        const float* __restrict__ w_phi,
        const float* __restrict__ w_g) {
    const int nb  = HWP / TP;                  // 72
    int blk  = blockIdx.x;
    int pb   = blk % nb;
    int t    = (blk / nb) % TC;
    int b    = blk / (nb * TC);
    int pix0 = pb * TP;

    __shared__ float xs[CC][TP];               // 16 KB

    const float* xb = x + ((long)(b * CC) * TT + (t + 1)) * HWP + pix0;
    for (int i = threadIdx.x; i < CC * TP; i += blockDim.x) {
        int c = i / TP, pp = i % TP;
        xs[c][pp] = xb[(long)c * TT * HWP + pp];
    }
    __syncthreads();

    int r = threadIdx.x;                       // output row 0..127
    const float* wr = (r < NH) ? (w_phi + r * CC) : (w_g + (r - NH) * CC);

    float acc[TP];
#pragma unroll
    for (int pp = 0; pp < TP; pp++) acc[pp] = 0.f;

    for (int c = 0; c < CC; c++) {
        float w = wr[c];
#pragma unroll
        for (int v = 0; v < TP / 4; v++) {     // float4 broadcast LDS
            float4 xv = *(const float4*)&xs[c][v * 4];
            acc[v * 4 + 0] += w * xv.x;
            acc[v * 4 + 1] += w * xv.y;
            acc[v * 4 + 2] += w * xv.z;
            acc[v * 4 + 3] += w * xv.w;
        }
    }

    float* ob = ((r < NH) ? g_phiT : g_gvT)
              + ((long)(b * NH + (r & (NH - 1))) * TC + t) * HWP + pix0;
#pragma unroll
    for (int pp = 0; pp < TP; pp += 4)
        *(float4*)(ob + pp) = make_float4(acc[pp], acc[pp+1], acc[pp+2], acc[pp+3]);
}

// ---------------------------------------------------------------------------
// Query projection (t=0): q = w_theta @ x -> g_q [b][pix][h]
// grid = B*(HWP/TP), block = 64
// ---------------------------------------------------------------------------
__global__ __launch_bounds__(64) void proj_q_kernel(
        const float* __restrict__ x,
        const float* __restrict__ w_theta) {
    const int nb  = HWP / TP;
    int blk  = blockIdx.x;
    int pb   = blk % nb;
    int b    = blk / nb;
    int pix0 = pb * TP;

    __shared__ float xs[CC][TP];

    const float* xb = x + ((long)(b * CC) * TT + 0) * HWP + pix0;
    for (int i = threadIdx.x; i < CC * TP; i += blockDim.x) {
        int c = i / TP, pp = i % TP;
        xs[c][pp] = xb[(long)c * TT * HWP + pp];
    }
    __syncthreads();

    int r = threadIdx.x;                       // 0..63
    const float* wr = w_theta + r * CC;

    float acc[TP];
#pragma unroll
    for (int pp = 0; pp < TP; pp++) acc[pp] = 0.f;

    for (int c = 0; c < CC; c++) {
        float w = wr[c];
#pragma unroll
        for (int v = 0; v < TP / 4; v++) {
            float4 xv = *(const float4*)&xs[c][v * 4];
            acc[v * 4 + 0] += w * xv.x;
            acc[v * 4 + 1] += w * xv.y;
            acc[v * 4 + 2] += w * xv.z;
            acc[v * 4 + 3] += w * xv.w;
        }
    }

    long base = ((long)b * HWP + pix0);
#pragma unroll
    for (int pp = 0; pp < TP; pp++) g_q[(base + pp) * NH + r] = acc[pp];
}

// ---------------------------------------------------------------------------
// Attention per query pixel: thread-per-key QK (no shuffles), softmax,
// branchless scrambled AV. block = 256, grid = B*HWP.
//   AV scramble: G[k,h'] = g(head=(64k+h')/196, key=(64k+h')%196)
// ---------------------------------------------------------------------------
__global__ __launch_bounds__(256) void attn_kernel() {
    int bp  = blockIdx.x;               // 0 .. B*HWP-1
    int b   = bp / HWP;
    int pix = bp % HWP;
    int y0  = pix / WW;
    int x0  = pix % WW;
    int tid  = threadIdx.x;
    int warp = tid >> 5;
    int lane = tid & 31;

    __shared__ float qs[NH];
    __shared__ float att[NK];
    __shared__ int   ntp[NK];          // tf*HWP + neighbor pixel
    __shared__ float ypart[4][NH];
    __shared__ float red[16];

    if (tid < NH) qs[tid] = g_q[((long)b * HWP + pix) * NH + tid];

    if (tid < NK) {
        int k   = tid;
        int tf  = k / 49;
        int off = k % 49;
        int dy  = off / 7 - PAD;
        int dx  = off % 7 - PAD;
        int ny  = min(max(y0 + dy, 0), HH - 1);
        int nx  = min(max(x0 + dx, 0), WW - 1);
        ntp[k] = tf * HWP + ny * WW + nx;
    }
    __syncthreads();

    // ---- QK: one thread per key; 64 independent L2 loads, no shuffles ----
    if (tid < NK) {
        const float* pb0 = g_phiT + (long)b * NH * FRAME + ntp[tid];
        float d = 0.f;
#pragma unroll 8
        for (int h = 0; h < NH; h++)
            d += qs[h] * pb0[h * FRAME];
        att[tid] = d * 8.0f;            // * sqrt(64)
    }
    __syncthreads();

    // ---- softmax over 196 (8 warps; inactive lanes feed identities) ----
    float v = (tid < NK) ? att[tid] : -1e30f;
    float m = v;
#pragma unroll
    for (int s = 16; s > 0; s >>= 1) m = fmaxf(m, __shfl_xor_sync(0xffffffffu, m, s));
    if (lane == 0) red[warp] = m;
    __syncthreads();
    if (tid == 0) {
        float mm = red[0];
#pragma unroll
        for (int w = 1; w < 8; w++) mm = fmaxf(mm, red[w]);
        red[8] = mm;
    }
    __syncthreads();
    m = red[8];

    float e = (tid < NK) ? __expf(v - m) : 0.f;
    float ssum = e;
#pragma unroll
    for (int s = 16; s > 0; s >>= 1) ssum += __shfl_xor_sync(0xffffffffu, ssum, s);
    if (lane == 0) red[warp] = ssum;
    __syncthreads();
    if (tid == 0) {
        float t2 = red[0];
#pragma unroll
        for (int w = 1; w < 8; w++) t2 += red[w];
        red[9] = 1.f / t2;
    }
    __syncthreads();
    if (tid < NK) att[tid] = e * red[9];
    __syncthreads();

    // ---- AV (scrambled), branchless const-div, 4-way k-split ----
    {
        int q = tid >> 6;                 // 0..3
        int h = tid & (NH - 1);
        int kbeg = q * 49;
        const float* gbase = g_gvT + (long)b * NH * FRAME;

        float acc = 0.f;
#pragma unroll 7
        for (int k = kbeg; k < kbeg + 49; k++) {
            int flat = k * NH + h;
            int hh = flat / NK;           // constant divisor -> branchless
            int kk = flat - hh * NK;
            acc += att[k] * gbase[hh * FRAME + ntp[kk]];
        }
        ypart[q][h] = acc;
    }
    __syncthreads();
    if (tid < NH)
        g_y[((long)b * HWP + pix) * NH + tid] =
            ypart[0][tid] + ypart[1][tid] + ypart[2][tid] + ypart[3][tid];
}

// ---------------------------------------------------------------------------
// Out projection + residual, honoring the reference's y.reshape scramble:
//   out[b,c,p2] = x[b,c,0,p2] + sum_h2 w_out[c,h2] * Y[b, h2*36 + p2/64, p2%64]
// block = 128 (c = tid); grid = B*NQ2*4 (16-pixel j-quarters).
// ---------------------------------------------------------------------------
#define JQ 16
__global__ __launch_bounds__(128) void outproj_kernel(
        const float* __restrict__ x,
        const float* __restrict__ w_out,
        float* __restrict__ out) {
    int blk = blockIdx.x;
    int jq  = blk & 3;
    int q2  = (blk >> 2) % NQ2;
    int b   = blk / (4 * NQ2);
    int j0  = jq * JQ;
    int tid = threadIdx.x;

    __shared__ float ys[NH][JQ];   // ys[h2][j] = Y[b, h2*36+q2, j0+j]

    for (int i = tid; i < NH * JQ; i += 128) {
        int h2 = i / JQ;
        int j  = i % JQ;
        ys[h2][j] = g_y[((long)b * HWP + h2 * NQ2 + q2) * NH + j0 + j];
    }
    __syncthreads();

    int c = tid;                                   // 0..127
    const float* wr = w_out + c * NH;

    float acc[JQ];
#pragma unroll
    for (int j = 0; j < JQ; j++) acc[j] = 0.f;

    for (int h2 = 0; h2 < NH; h2++) {
        float w = wr[h2];
#pragma unroll
        for (int v = 0; v < JQ / 4; v++) {
            float4 yv = *(const float4*)&ys[h2][v * 4];
            acc[v * 4 + 0] += w * yv.x;
            acc[v * 4 + 1] += w * yv.y;
            acc[v * 4 + 2] += w * yv.z;
            acc[v * 4 + 3] += w * yv.w;
        }
    }

    long pixbase = (long)q2 * 64 + j0;
    const float* xr   = x   + (((long)(b * CC + c)) * TT + 0) * HWP + pixbase;
    float*       orow = out + ((long)(b * CC + c)) * HWP + pixbase;
#pragma unroll
    for (int j = 0; j < JQ; j += 4) {
        float4 xv = *(const float4*)(xr + j);
        *(float4*)(orow + j) = make_float4(xv.x + acc[j],     xv.y + acc[j + 1],
                                           xv.z + acc[j + 2], xv.w + acc[j + 3]);
    }
}

extern "C" void kernel_launch(void* const* d_in, const int* in_sizes, int n_in,
                              void* d_out, int out_size) {
    const float* x       = (const float*)d_in[0];
    const float* w_theta = (const float*)d_in[1];
    const float* w_phi   = (const float*)d_in[2];
    const float* w_g     = (const float*)d_in[3];
    const float* w_out   = (const float*)d_in[4];
    float* out = (float*)d_out;

    proj_ctx_kernel<<<BB * TC * (HWP / TP), 128>>>(x, w_phi, w_g);
    proj_q_kernel<<<BB * (HWP / TP), 64>>>(x, w_theta);
    attn_kernel<<<BB * HWP, 256>>>();
    outproj_kernel<<<BB * NQ2 * 4, 128>>>(x, w_out, out);
}